// round 6
// baseline (speedup 1.0000x reference)
#include <cuda_runtime.h>
#include <cuda_bf16.h>
#include <cstdint>
#include <math.h>

// Problem constants
#define B_ 4
#define S_ 2048
#define E_ 1024
#define D_ 1024

// GEMM tiling
#define BM 128
#define BN 128
#define BK 32
#define PK 40            // smem k-pitch in bf16 elems (bank-spread, 16B-aligned rows)
#define NTHREADS 256
// One pipeline stage = 4 tile buffers of BM*PK bf16 = 40960 B; double-buffered.
#define STAGE_ELEMS (4 * BM * PK)
#define SMEM_BYTES (2 * STAGE_ELEMS * 2)

// Scratch (static device arrays; cudaMalloc is forbidden)
static __device__ float g_Q[(size_t)B_ * S_ * D_];
static __device__ float g_K[(size_t)B_ * S_ * D_];
static __device__ float g_Vt[(size_t)B_ * D_ * S_];   // V stored transposed [b][d][s]
static __device__ float g_A[(size_t)B_ * S_ * S_];

__device__ __forceinline__ unsigned int smem_u32(const void* p) {
    return (unsigned int)__cvta_generic_to_shared(p);
}

#define LDSM_X4(R0, R1, R2, R3, ADDR)                                          \
    asm volatile("ldmatrix.sync.aligned.m8n8.x4.shared.b16 {%0,%1,%2,%3}, [%4];" \
                 : "=r"(R0), "=r"(R1), "=r"(R2), "=r"(R3) : "r"(ADDR))

#define LDSM_X2(R0, R1, ADDR)                                                  \
    asm volatile("ldmatrix.sync.aligned.m8n8.x2.shared.b16 {%0,%1}, [%2];"      \
                 : "=r"(R0), "=r"(R1) : "r"(ADDR))

#define MMA_BF16(D, A0, A1, A2, A3, Bq0, Bq1)                                  \
    asm volatile("mma.sync.aligned.m16n8k16.row.col.f32.bf16.bf16.f32 "         \
                 "{%0,%1,%2,%3}, {%4,%5,%6,%7}, {%8,%9}, {%0,%1,%2,%3};"        \
                 : "+f"(D[0]), "+f"(D[1]), "+f"(D[2]), "+f"(D[3])               \
                 : "r"(A0), "r"(A1), "r"(A2), "r"(A3), "r"(Bq0), "r"(Bq1))

// Split a float4 into hi/lo bf16 pairs and store as two bf162 each.
__device__ __forceinline__ void split_store(__nv_bfloat16* hi, __nv_bfloat16* lo,
                                            float4 v) {
    __nv_bfloat16 h0 = __float2bfloat16(v.x);
    __nv_bfloat16 h1 = __float2bfloat16(v.y);
    __nv_bfloat16 h2 = __float2bfloat16(v.z);
    __nv_bfloat16 h3 = __float2bfloat16(v.w);
    __nv_bfloat16 l0 = __float2bfloat16(v.x - __bfloat162float(h0));
    __nv_bfloat16 l1 = __float2bfloat16(v.y - __bfloat162float(h1));
    __nv_bfloat16 l2 = __float2bfloat16(v.z - __bfloat162float(h2));
    __nv_bfloat16 l3 = __float2bfloat16(v.w - __bfloat162float(h3));
    *(__nv_bfloat162*)(hi + 0) = __nv_bfloat162(h0, h1);
    *(__nv_bfloat162*)(hi + 2) = __nv_bfloat162(h2, h3);
    *(__nv_bfloat162*)(lo + 0) = __nv_bfloat162(l0, l1);
    *(__nv_bfloat162*)(lo + 2) = __nv_bfloat162(l2, l3);
}

// ---------------------------------------------------------------------------
// 128x128x32 NT GEMM tile via bf16 split-precision tensor-core mma.
// D = A(hi+lo) @ B(hi+lo)^T  ~= Ah*Bh + Ah*Bl + Al*Bh   (fp32 accumulate)
// DOUBLE-BUFFERED dynamic smem: one __syncthreads per K-slab; the split
// convert+store for slab k+1 overlaps with mma issue on slab k.
//   HAS_BIAS : add bias[col] in epilogue
//   KLIMIT   : clamp K loop to (blockIdx.x+1)*BM (causal AV gemm)
//   TRANSC   : store C transposed per-batch ([d][s], for V)
// ---------------------------------------------------------------------------
template <bool HAS_BIAS, bool KLIMIT, bool TRANSC>
__device__ __forceinline__ void gemm_body(
    const float* __restrict__ A, const float* __restrict__ Bm,
    const float* __restrict__ bias, float* __restrict__ C,
    int K, int ldb, int ldc, float scale)
{
    extern __shared__ __nv_bfloat16 smem[];

    const int t    = threadIdx.x;
    const int lane = t & 31;
    const int wid  = t >> 5;
    const int wm   = (wid >> 2) * 64;   // warp row base within tile (0/64)
    const int wn   = (wid & 3) * 32;    // warp col base within tile (0..96)

    const int row0 = blockIdx.x * BM;
    const int col0 = blockIdx.y * BN;

    const int fr = t >> 3;              // 0..31  (gmem load row)
    const int fc = (t & 7) * 4;         // 0..28  (gmem load col)

    int kmax = K;
    if (KLIMIT) {
        int lim = (blockIdx.x + 1) * BM;
        kmax = lim < K ? lim : K;
    }

    float acc[4][4][4];
#pragma unroll
    for (int i = 0; i < 4; i++)
#pragma unroll
        for (int j = 0; j < 4; j++)
#pragma unroll
            for (int r = 0; r < 4; r++) acc[i][j][r] = 0.f;

    float4 ra[4], rb[4];

    auto fetch = [&](int k0) {
#pragma unroll
        for (int i = 0; i < 4; i++) {
            ra[i] = *(const float4*)(A  + (size_t)(row0 + fr + 32 * i) * K   + (k0 + fc));
            rb[i] = *(const float4*)(Bm + (size_t)(col0 + fr + 32 * i) * ldb + (k0 + fc));
        }
    };
    auto store = [&](int buf) {
        __nv_bfloat16* base = smem + buf * STAGE_ELEMS;
        __nv_bfloat16* Ah = base;
        __nv_bfloat16* Al = base + BM * PK;
        __nv_bfloat16* Bh = base + 2 * BM * PK;
        __nv_bfloat16* Bl = base + 3 * BM * PK;
#pragma unroll
        for (int i = 0; i < 4; i++) {
            const int r = fr + 32 * i;
            split_store(&Ah[r * PK + fc], &Al[r * PK + fc], ra[i]);
            split_store(&Bh[r * PK + fc], &Bl[r * PK + fc], rb[i]);
        }
    };
    auto compute = [&](int buf) {
        __nv_bfloat16* base = smem + buf * STAGE_ELEMS;
        __nv_bfloat16* Ah = base;
        __nv_bfloat16* Al = base + BM * PK;
        __nv_bfloat16* Bh = base + 2 * BM * PK;
        __nv_bfloat16* Bl = base + 3 * BM * PK;
#pragma unroll
        for (int kk = 0; kk < 2; kk++) {
            unsigned int ah[4][4], al[4][4], bh[4][2], bl[4][2];
            const int arow = wm + (lane & 15);
            const int acol = kk * 16 + (lane >> 4) * 8;
#pragma unroll
            for (int mt = 0; mt < 4; mt++) {
                const int off = (arow + mt * 16) * PK + acol;
                LDSM_X4(ah[mt][0], ah[mt][1], ah[mt][2], ah[mt][3], smem_u32(&Ah[off]));
                LDSM_X4(al[mt][0], al[mt][1], al[mt][2], al[mt][3], smem_u32(&Al[off]));
            }
            const int brow = wn + (lane & 7);
            const int bcol = kk * 16 + ((lane >> 3) & 1) * 8;
#pragma unroll
            for (int nt = 0; nt < 4; nt++) {
                const int off = (brow + nt * 8) * PK + bcol;
                LDSM_X2(bh[nt][0], bh[nt][1], smem_u32(&Bh[off]));
                LDSM_X2(bl[nt][0], bl[nt][1], smem_u32(&Bl[off]));
            }
#pragma unroll
            for (int mt = 0; mt < 4; mt++)
#pragma unroll
                for (int nt = 0; nt < 4; nt++) {
                    MMA_BF16(acc[mt][nt], ah[mt][0], ah[mt][1], ah[mt][2], ah[mt][3],
                             bh[nt][0], bh[nt][1]);
                    MMA_BF16(acc[mt][nt], ah[mt][0], ah[mt][1], ah[mt][2], ah[mt][3],
                             bl[nt][0], bl[nt][1]);
                    MMA_BF16(acc[mt][nt], al[mt][0], al[mt][1], al[mt][2], al[mt][3],
                             bh[nt][0], bh[nt][1]);
                }
        }
    };

    // ---- double-buffered main loop: one barrier per K-slab ----
    int buf = 0;
    fetch(0);
    store(0);
    __syncthreads();
    for (int k0 = BK; k0 < kmax; k0 += BK) {
        fetch(k0);          // gmem -> regs (next slab)
        compute(buf);       // mma on current slab
        store(buf ^ 1);     // regs -> other buffer (overlaps with nothing blocking)
        __syncthreads();
        buf ^= 1;
    }
    compute(buf);

    // ---- epilogue ----
    const int g = lane >> 2;
    const int q = lane & 3;
#pragma unroll
    for (int mt = 0; mt < 4; mt++) {
#pragma unroll
        for (int nt = 0; nt < 4; nt++) {
            const int r = row0 + wm + mt * 16 + g;
            const int c = col0 + wn + nt * 8 + 2 * q;
            float v0 = acc[mt][nt][0] * scale;
            float v1 = acc[mt][nt][1] * scale;
            float v2 = acc[mt][nt][2] * scale;
            float v3 = acc[mt][nt][3] * scale;
            if (HAS_BIAS) {
                const float b0 = bias[c], b1 = bias[c + 1];
                v0 += b0; v1 += b1; v2 += b0; v3 += b1;
            }
            if (TRANSC) {
                const int batch = row0 >> 11;          // 128-row tiles never straddle batches
                const size_t base = (size_t)batch * D_ * S_;
                const int s = r & (S_ - 1);
                C[base + (size_t)c * S_ + s]           = v0;
                C[base + (size_t)(c + 1) * S_ + s]     = v1;
                C[base + (size_t)c * S_ + s + 8]       = v2;
                C[base + (size_t)(c + 1) * S_ + s + 8] = v3;
            } else {
                *(float2*)&C[(size_t)r * ldc + c]       = make_float2(v0, v1);
                *(float2*)&C[(size_t)(r + 8) * ldc + c] = make_float2(v2, v3);
            }
        }
    }
}

// ---------------------------------------------------------------------------
// Stage 1: Q/K/V = X @ W^T + b. V is stored transposed so the AV gemm is NT.
// ---------------------------------------------------------------------------
__global__ __launch_bounds__(NTHREADS) void qkv_kernel(
    const float* __restrict__ X,
    const float* __restrict__ Wq, const float* __restrict__ bq,
    const float* __restrict__ Wk, const float* __restrict__ bk,
    const float* __restrict__ Wv, const float* __restrict__ bv)
{
    if (blockIdx.z == 0)
        gemm_body<true, false, false>(X, Wq, bq, g_Q, E_, E_, D_, 1.0f);
    else if (blockIdx.z == 1)
        gemm_body<true, false, false>(X, Wk, bk, g_K, E_, E_, D_, 1.0f);
    else
        gemm_body<true, false, true>(X, Wv, bv, g_Vt, E_, E_, D_, 1.0f);
}

// ---------------------------------------------------------------------------
// Stage 2: scores A = (Q @ K^T) / sqrt(D); tiles above the diagonal skipped.
// ---------------------------------------------------------------------------
__global__ __launch_bounds__(NTHREADS) void scores_kernel()
{
    if (blockIdx.y > blockIdx.x) return;
    const size_t bo = (size_t)blockIdx.z * S_ * D_;
    gemm_body<false, false, false>(g_Q + bo, g_K + bo, nullptr,
                                   g_A + (size_t)blockIdx.z * S_ * S_,
                                   D_, D_, S_, 0.03125f /* 1/sqrt(1024) */);
}

// ---------------------------------------------------------------------------
// Stage 3: causal row softmax; zero-fills past the diagonal so AV can read
// clamped full tiles.
// ---------------------------------------------------------------------------
__global__ __launch_bounds__(256) void softmax_kernel()
{
    const int gid = blockIdx.x;                 // b*S + m
    float* row = g_A + (size_t)gid * S_;
    const int m = gid & (S_ - 1);
    const int n = m + 1;
    const int t = threadIdx.x;
    __shared__ float red[8];

    float mx = -INFINITY;
    for (int i = t; i < n; i += 256) mx = fmaxf(mx, row[i]);
#pragma unroll
    for (int o = 16; o > 0; o >>= 1) mx = fmaxf(mx, __shfl_xor_sync(~0u, mx, o));
    if ((t & 31) == 0) red[t >> 5] = mx;
    __syncthreads();
    mx = red[0];
#pragma unroll
    for (int w = 1; w < 8; w++) mx = fmaxf(mx, red[w]);
    __syncthreads();

    float s = 0.f;
    for (int i = t; i < n; i += 256) {
        float e = __expf(row[i] - mx);
        row[i] = e;
        s += e;
    }
#pragma unroll
    for (int o = 16; o > 0; o >>= 1) s += __shfl_xor_sync(~0u, s, o);
    if ((t & 31) == 0) red[t >> 5] = s;
    __syncthreads();
    s = 0.f;
#pragma unroll
    for (int w = 0; w < 8; w++) s += red[w];
    const float inv = 1.f / s;

    for (int i = t; i < S_; i += 256) row[i] = (i < n) ? row[i] * inv : 0.f;
}

// ---------------------------------------------------------------------------
// Stage 4: O = A @ V = A @ Vt^T (NT gemm), K-loop clamped causally.
// ---------------------------------------------------------------------------
__global__ __launch_bounds__(NTHREADS) void av_kernel(float* __restrict__ out)
{
    const size_t b = blockIdx.z;
    gemm_body<false, true, false>(g_A + b * (size_t)S_ * S_,
                                  g_Vt + b * (size_t)D_ * S_, nullptr,
                                  out + b * (size_t)S_ * D_,
                                  S_, S_, D_, 1.0f);
}

// ---------------------------------------------------------------------------
// Inputs (metadata order): X, Wq, bq, Wk, bk, Wv, bv, mask (mask is static
// triu(k=1) -> applied analytically).
// cudaFuncSetAttribute is a host-side function attribute (not a stream op):
// safe under graph capture, no allocation.
// ---------------------------------------------------------------------------
extern "C" void kernel_launch(void* const* d_in, const int* in_sizes, int n_in,
                              void* d_out, int out_size)
{
    const float* X  = (const float*)d_in[0];
    const float* Wq = (const float*)d_in[1];
    const float* bq = (const float*)d_in[2];
    const float* Wk = (const float*)d_in[3];
    const float* bk = (const float*)d_in[4];
    const float* Wv = (const float*)d_in[5];
    const float* bv = (const float*)d_in[6];
    float* out = (float*)d_out;

    cudaFuncSetAttribute(qkv_kernel,    cudaFuncAttributeMaxDynamicSharedMemorySize, SMEM_BYTES);
    cudaFuncSetAttribute(scores_kernel, cudaFuncAttributeMaxDynamicSharedMemorySize, SMEM_BYTES);
    cudaFuncSetAttribute(av_kernel,     cudaFuncAttributeMaxDynamicSharedMemorySize, SMEM_BYTES);

    dim3 blk(NTHREADS);
    qkv_kernel<<<dim3((B_ * S_) / BM, D_ / BN, 3), blk, SMEM_BYTES>>>(X, Wq, bq, Wk, bk, Wv, bv);
    scores_kernel<<<dim3(S_ / BM, S_ / BN, B_), blk, SMEM_BYTES>>>();
    softmax_kernel<<<dim3(B_ * S_), 256>>>();
    av_kernel<<<dim3(S_ / BM, D_ / BN, B_), blk, SMEM_BYTES>>>(out);
}

// round 8
// speedup vs baseline: 1.0796x; 1.0796x over previous
#include <cuda_runtime.h>
#include <cuda_bf16.h>
#include <cstdint>
#include <math.h>

// Problem constants
#define B_ 4
#define S_ 2048
#define E_ 1024
#define D_ 1024

// GEMM tiling
#define BM 128
#define BN 128
#define BK 32
#define PK 40                        // smem k-pitch in bf16 elems
#define NTHREADS 256

#define SUB_ELEMS (BM * PK)          // one operand tile: 5120 bf16 = 10240 B
#define STAGE_ELEMS (4 * SUB_ELEMS)  // Ah,Al,Bh,Bl per stage = 40960 B
#define SMEM_BYTES (2 * STAGE_ELEMS * 2)   // 2 stages = 81920 B

// ---------------- gmem scratch (static device arrays) ----------------
static __device__ __nv_bfloat16 g_Xh[(size_t)B_ * S_ * E_];
static __device__ __nv_bfloat16 g_Xl[(size_t)B_ * S_ * E_];
static __device__ __nv_bfloat16 g_Wh[3 * (size_t)D_ * E_];
static __device__ __nv_bfloat16 g_Wl[3 * (size_t)D_ * E_];
static __device__ __nv_bfloat16 g_Qh[(size_t)B_ * S_ * D_];
static __device__ __nv_bfloat16 g_Ql[(size_t)B_ * S_ * D_];
static __device__ __nv_bfloat16 g_Kh[(size_t)B_ * S_ * D_];
static __device__ __nv_bfloat16 g_Kl[(size_t)B_ * S_ * D_];
static __device__ __nv_bfloat16 g_Vth[(size_t)B_ * D_ * S_];  // V transposed [b][d][s]
static __device__ __nv_bfloat16 g_Vtl[(size_t)B_ * D_ * S_];
static __device__ float         g_A [(size_t)B_ * S_ * S_];   // raw scores
static __device__ __nv_bfloat16 g_Ph[(size_t)B_ * S_ * S_];   // softmax probs hi/lo
static __device__ __nv_bfloat16 g_Pl[(size_t)B_ * S_ * S_];

__device__ __forceinline__ unsigned smem_u32(const void* p) {
    return (unsigned)__cvta_generic_to_shared(p);
}
__device__ __forceinline__ void cp16(void* sdst, const void* gsrc) {
    asm volatile("cp.async.cg.shared.global [%0], [%1], 16;"
                 :: "r"(smem_u32(sdst)), "l"(gsrc));
}
#define CP_COMMIT() asm volatile("cp.async.commit_group;" ::: "memory")

#define LDSM_X4(R0, R1, R2, R3, ADDR)                                          \
    asm volatile("ldmatrix.sync.aligned.m8n8.x4.shared.b16 {%0,%1,%2,%3}, [%4];" \
                 : "=r"(R0), "=r"(R1), "=r"(R2), "=r"(R3) : "r"(ADDR))
#define LDSM_X2(R0, R1, ADDR)                                                  \
    asm volatile("ldmatrix.sync.aligned.m8n8.x2.shared.b16 {%0,%1}, [%2];"      \
                 : "=r"(R0), "=r"(R1) : "r"(ADDR))
#define MMA_BF16(D, A0, A1, A2, A3, Bq0, Bq1)                                  \
    asm volatile("mma.sync.aligned.m16n8k16.row.col.f32.bf16.bf16.f32 "         \
                 "{%0,%1,%2,%3}, {%4,%5,%6,%7}, {%8,%9}, {%0,%1,%2,%3};"        \
                 : "+f"(D[0]), "+f"(D[1]), "+f"(D[2]), "+f"(D[3])               \
                 : "r"(A0), "r"(A1), "r"(A2), "r"(A3), "r"(Bq0), "r"(Bq1))

__device__ __forceinline__ __nv_bfloat16 lo_of(float v, __nv_bfloat16 h) {
    return __float2bfloat16(v - __bfloat162float(h));
}

// ---------------------------------------------------------------------------
// Pre-split fp32 -> bf16 (hi, lo) in gmem. n4 = element count / 4.
// ---------------------------------------------------------------------------
__global__ void split_kernel(const float* __restrict__ src,
                             __nv_bfloat16* __restrict__ hi,
                             __nv_bfloat16* __restrict__ lo, int n4)
{
    int i = blockIdx.x * blockDim.x + threadIdx.x;
    if (i >= n4) return;
    float4 v = ((const float4*)src)[i];
    __nv_bfloat16 h0 = __float2bfloat16(v.x), h1 = __float2bfloat16(v.y);
    __nv_bfloat16 h2 = __float2bfloat16(v.z), h3 = __float2bfloat16(v.w);
    *(__nv_bfloat162*)(hi + 4 * i)     = __nv_bfloat162(h0, h1);
    *(__nv_bfloat162*)(hi + 4 * i + 2) = __nv_bfloat162(h2, h3);
    *(__nv_bfloat162*)(lo + 4 * i)     = __nv_bfloat162(lo_of(v.x, h0), lo_of(v.y, h1));
    *(__nv_bfloat162*)(lo + 4 * i + 2) = __nv_bfloat162(lo_of(v.z, h2), lo_of(v.w, h3));
}

// ---------------------------------------------------------------------------
// 128x128x32 NT GEMM tile, split-bf16 3-term mma.sync, 2-stage cp.async
// pipeline. Operands are pre-split bf16 hi/lo in gmem (K-contiguous rows).
//   OMODE 0: fp32 out (Cf)    OMODE 1: bf16 hi/lo out (Ch/Cl, row-major)
//   OMODE 2: bf16 hi/lo out transposed per-batch ([d][s], for Vt)
// ---------------------------------------------------------------------------
template <int OMODE, bool HAS_BIAS, bool KLIMIT>
__device__ __forceinline__ void gemm_body(
    const __nv_bfloat16* __restrict__ Ahg, const __nv_bfloat16* __restrict__ Alg,
    const __nv_bfloat16* __restrict__ Bhg, const __nv_bfloat16* __restrict__ Blg,
    const float* __restrict__ bias, float* __restrict__ Cf,
    __nv_bfloat16* __restrict__ Ch, __nv_bfloat16* __restrict__ Cl,
    int K, int ldb, int ldc, float scale)
{
    extern __shared__ __nv_bfloat16 smem[];
    const int t = threadIdx.x, lane = t & 31, wid = t >> 5;
    const int wm = (wid >> 2) * 64;     // warp row base (0/64)
    const int wn = (wid & 3) * 32;      // warp col base (0..96)
    const int row0 = blockIdx.x * BM, col0 = blockIdx.y * BN;

    int kmax = K;
    if (KLIMIT) { int lim = (blockIdx.x + 1) * BM; kmax = lim < K ? lim : K; }
    const int chunks = kmax / BK;       // >= 4 always

    float acc[4][4][4];
#pragma unroll
    for (int i = 0; i < 4; i++)
#pragma unroll
        for (int j = 0; j < 4; j++)
#pragma unroll
            for (int r = 0; r < 4; r++) acc[i][j][r] = 0.f;

    auto issue = [&](int c, int b) {
        __nv_bfloat16* st = smem + b * STAGE_ELEMS;
        const int k0 = c * BK;
#pragma unroll
        for (int h = 0; h < 2; h++) {
            const int cid = t + 256 * h;       // 0..511
            const int row = cid >> 2;          // 0..127
            const int kc  = (cid & 3) * 8;     // 0,8,16,24 (16B chunks)
            __nv_bfloat16* s = st + row * PK + kc;
            const size_t ga = (size_t)(row0 + row) * K   + k0 + kc;
            const size_t gb = (size_t)(col0 + row) * ldb + k0 + kc;
            cp16(s,                 Ahg + ga);
            cp16(s + SUB_ELEMS,     Alg + ga);
            cp16(s + 2 * SUB_ELEMS, Bhg + gb);
            cp16(s + 3 * SUB_ELEMS, Blg + gb);
        }
    };

    auto compute = [&](int b) {
        __nv_bfloat16* Ah = smem + b * STAGE_ELEMS;
        __nv_bfloat16* Al = Ah + SUB_ELEMS;
        __nv_bfloat16* Bh = Ah + 2 * SUB_ELEMS;
        __nv_bfloat16* Bl = Ah + 3 * SUB_ELEMS;
#pragma unroll
        for (int kk = 0; kk < 2; kk++) {
            unsigned ah[4][4], al[4][4], bh[4][2], bl[4][2];
            const int arow = wm + (lane & 15);
            const int acol = kk * 16 + (lane >> 4) * 8;
#pragma unroll
            for (int mt = 0; mt < 4; mt++) {
                const int off = (arow + mt * 16) * PK + acol;
                LDSM_X4(ah[mt][0], ah[mt][1], ah[mt][2], ah[mt][3], smem_u32(&Ah[off]));
                LDSM_X4(al[mt][0], al[mt][1], al[mt][2], al[mt][3], smem_u32(&Al[off]));
            }
            const int brow = wn + (lane & 7);
            const int bcol = kk * 16 + ((lane >> 3) & 1) * 8;
#pragma unroll
            for (int nt = 0; nt < 4; nt++) {
                const int off = (brow + nt * 8) * PK + bcol;
                LDSM_X2(bh[nt][0], bh[nt][1], smem_u32(&Bh[off]));
                LDSM_X2(bl[nt][0], bl[nt][1], smem_u32(&Bl[off]));
            }
#pragma unroll
            for (int mt = 0; mt < 4; mt++)
#pragma unroll
                for (int nt = 0; nt < 4; nt++) {
                    MMA_BF16(acc[mt][nt], ah[mt][0], ah[mt][1], ah[mt][2], ah[mt][3],
                             bh[nt][0], bh[nt][1]);
                    MMA_BF16(acc[mt][nt], ah[mt][0], ah[mt][1], ah[mt][2], ah[mt][3],
                             bl[nt][0], bl[nt][1]);
                    MMA_BF16(acc[mt][nt], al[mt][0], al[mt][1], al[mt][2], al[mt][3],
                             bh[nt][0], bh[nt][1]);
                }
        }
    };

    // ---- 2-stage cp.async mainloop ----
    issue(0, 0); CP_COMMIT();
    issue(1, 1); CP_COMMIT();
    for (int c = 0; c < chunks; c++) {
        if (c + 1 < chunks)
            asm volatile("cp.async.wait_group 1;" ::: "memory");
        else
            asm volatile("cp.async.wait_group 0;" ::: "memory");
        __syncthreads();
        compute(c & 1);
        __syncthreads();
        if (c + 2 < chunks) { issue(c + 2, c & 1); CP_COMMIT(); }
    }

    // ---- epilogue ----
    const int g = lane >> 2, q = lane & 3;
#pragma unroll
    for (int mt = 0; mt < 4; mt++) {
#pragma unroll
        for (int nt = 0; nt < 4; nt++) {
            const int r = row0 + wm + mt * 16 + g;
            const int c = col0 + wn + nt * 8 + 2 * q;
            float v0 = acc[mt][nt][0] * scale;
            float v1 = acc[mt][nt][1] * scale;
            float v2 = acc[mt][nt][2] * scale;
            float v3 = acc[mt][nt][3] * scale;
            if (HAS_BIAS) {
                const float b0 = bias[c], b1 = bias[c + 1];
                v0 += b0; v1 += b1; v2 += b0; v3 += b1;
            }
            if (OMODE == 0) {
                *(float2*)&Cf[(size_t)r * ldc + c]       = make_float2(v0, v1);
                *(float2*)&Cf[(size_t)(r + 8) * ldc + c] = make_float2(v2, v3);
            } else {
                __nv_bfloat16 h0 = __float2bfloat16(v0), h1 = __float2bfloat16(v1);
                __nv_bfloat16 h2 = __float2bfloat16(v2), h3 = __float2bfloat16(v3);
                __nv_bfloat16 l0 = lo_of(v0, h0), l1 = lo_of(v1, h1);
                __nv_bfloat16 l2 = lo_of(v2, h2), l3 = lo_of(v3, h3);
                if (OMODE == 1) {
                    *(__nv_bfloat162*)&Ch[(size_t)r * ldc + c]       = __nv_bfloat162(h0, h1);
                    *(__nv_bfloat162*)&Ch[(size_t)(r + 8) * ldc + c] = __nv_bfloat162(h2, h3);
                    *(__nv_bfloat162*)&Cl[(size_t)r * ldc + c]       = __nv_bfloat162(l0, l1);
                    *(__nv_bfloat162*)&Cl[(size_t)(r + 8) * ldc + c] = __nv_bfloat162(l2, l3);
                } else {
                    const int batch = row0 >> 11;   // 128-row tiles never straddle batches
                    const size_t base = (size_t)batch * D_ * S_;
                    const int s = r & (S_ - 1);
                    Ch[base + (size_t)c * S_ + s]           = h0;
                    Ch[base + (size_t)(c + 1) * S_ + s]     = h1;
                    Ch[base + (size_t)c * S_ + s + 8]       = h2;
                    Ch[base + (size_t)(c + 1) * S_ + s + 8] = h3;
                    Cl[base + (size_t)c * S_ + s]           = l0;
                    Cl[base + (size_t)(c + 1) * S_ + s]     = l1;
                    Cl[base + (size_t)c * S_ + s + 8]       = l2;
                    Cl[base + (size_t)(c + 1) * S_ + s + 8] = l3;
                }
            }
        }
    }
}

// ---------------------------------------------------------------------------
// Stage 1: Q/K/V = X @ W^T + b from pre-split X/W; writes split outputs.
// ---------------------------------------------------------------------------
__global__ __launch_bounds__(NTHREADS) void qkv_kernel(
    const float* __restrict__ bq, const float* __restrict__ bk,
    const float* __restrict__ bv)
{
    const size_t wo = (size_t)blockIdx.z * D_ * E_;
    if (blockIdx.z == 0)
        gemm_body<1, true, false>(g_Xh, g_Xl, g_Wh + wo, g_Wl + wo, bq,
                                  nullptr, g_Qh, g_Ql, E_, E_, D_, 1.0f);
    else if (blockIdx.z == 1)
        gemm_body<1, true, false>(g_Xh, g_Xl, g_Wh + wo, g_Wl + wo, bk,
                                  nullptr, g_Kh, g_Kl, E_, E_, D_, 1.0f);
    else
        gemm_body<2, true, false>(g_Xh, g_Xl, g_Wh + wo, g_Wl + wo, bv,
                                  nullptr, g_Vth, g_Vtl, E_, E_, D_, 1.0f);
}

// ---------------------------------------------------------------------------
// Stage 2: scores A = (Q @ K^T) / sqrt(D); tiles above the diagonal skipped.
// ---------------------------------------------------------------------------
__global__ __launch_bounds__(NTHREADS) void scores_kernel()
{
    if (blockIdx.y > blockIdx.x) return;
    const size_t bo = (size_t)blockIdx.z * S_ * D_;
    gemm_body<0, false, false>(g_Qh + bo, g_Ql + bo, g_Kh + bo, g_Kl + bo, nullptr,
                               g_A + (size_t)blockIdx.z * S_ * S_, nullptr, nullptr,
                               D_, D_, S_, 0.03125f /* 1/sqrt(1024) */);
}

// ---------------------------------------------------------------------------
// Stage 3: causal softmax, writing split bf16 probabilities (zero-filled
// past the diagonal so AV can read clamped full tiles).
// ---------------------------------------------------------------------------
__global__ __launch_bounds__(256) void softmax_kernel()
{
    const int gid = blockIdx.x;                 // b*S + m
    const float* row = g_A + (size_t)gid * S_;
    __nv_bfloat16* ph = g_Ph + (size_t)gid * S_;
    __nv_bfloat16* pl = g_Pl + (size_t)gid * S_;
    const int m = gid & (S_ - 1);
    const int n = m + 1;
    const int t = threadIdx.x;
    __shared__ float red[8];

    float mx = -INFINITY;
    for (int i = t; i < n; i += 256) mx = fmaxf(mx, row[i]);
#pragma unroll
    for (int o = 16; o > 0; o >>= 1) mx = fmaxf(mx, __shfl_xor_sync(~0u, mx, o));
    if ((t & 31) == 0) red[t >> 5] = mx;
    __syncthreads();
    mx = red[0];
#pragma unroll
    for (int w = 1; w < 8; w++) mx = fmaxf(mx, red[w]);
    __syncthreads();

    float s = 0.f;
    for (int i = t; i < n; i += 256) s += __expf(row[i] - mx);
#pragma unroll
    for (int o = 16; o > 0; o >>= 1) s += __shfl_xor_sync(~0u, s, o);
    if ((t & 31) == 0) red[t >> 5] = s;
    __syncthreads();
    s = 0.f;
#pragma unroll
    for (int w = 0; w < 8; w++) s += red[w];
    const float inv = 1.f / s;

    for (int i = t; i < S_; i += 256) {
        float p = (i < n) ? __expf(row[i] - mx) * inv : 0.f;
        __nv_bfloat16 h = __float2bfloat16(p);
        ph[i] = h;
        pl[i] = lo_of(p, h);
    }
}

// ---------------------------------------------------------------------------
// Stage 4: O = P @ Vt^T (NT gemm), K-loop clamped causally.
// ---------------------------------------------------------------------------
__global__ __launch_bounds__(NTHREADS) void av_kernel(float* __restrict__ out)
{
    const size_t b = blockIdx.z;
    gemm_body<0, false, true>(g_Ph + b * (size_t)S_ * S_, g_Pl + b * (size_t)S_ * S_,
                              g_Vth + b * (size_t)D_ * S_, g_Vtl + b * (size_t)D_ * S_,
                              nullptr, out + b * (size_t)S_ * D_, nullptr, nullptr,
                              S_, S_, D_, 1.0f);
}

// ---------------------------------------------------------------------------
// Inputs (metadata order): X, Wq, bq, Wk, bk, Wv, bv, mask (mask is static
// triu(k=1) -> applied analytically). cudaFuncSetAttribute is a host-side
// function attribute, safe under graph capture.
// ---------------------------------------------------------------------------
extern "C" void kernel_launch(void* const* d_in, const int* in_sizes, int n_in,
                              void* d_out, int out_size)
{
    const float* X  = (const float*)d_in[0];
    const float* Wq = (const float*)d_in[1];
    const float* bq = (const float*)d_in[2];
    const float* Wk = (const float*)d_in[3];
    const float* bk = (const float*)d_in[4];
    const float* Wv = (const float*)d_in[5];
    const float* bv = (const float*)d_in[6];
    float* out = (float*)d_out;

    cudaFuncSetAttribute(qkv_kernel,    cudaFuncAttributeMaxDynamicSharedMemorySize, SMEM_BYTES);
    cudaFuncSetAttribute(scores_kernel, cudaFuncAttributeMaxDynamicSharedMemorySize, SMEM_BYTES);
    cudaFuncSetAttribute(av_kernel,     cudaFuncAttributeMaxDynamicSharedMemorySize, SMEM_BYTES);

    __nv_bfloat16 *xh, *xl, *wh, *wl;
    cudaGetSymbolAddress((void**)&xh, g_Xh);
    cudaGetSymbolAddress((void**)&xl, g_Xl);
    cudaGetSymbolAddress((void**)&wh, g_Wh);
    cudaGetSymbolAddress((void**)&wl, g_Wl);

    const int xn4 = B_ * S_ * E_ / 4;          // 2M
    const int wn4 = D_ * E_ / 4;               // 256K
    split_kernel<<<(xn4 + 255) / 256, 256>>>(X, xh, xl, xn4);
    split_kernel<<<(wn4 + 255) / 256, 256>>>(Wq, wh,               wl,               wn4);
    split_kernel<<<(wn4 + 255) / 256, 256>>>(Wk, wh + D_ * E_,     wl + D_ * E_,     wn4);
    split_kernel<<<(wn4 + 255) / 256, 256>>>(Wv, wh + 2 * D_ * E_, wl + 2 * D_ * E_, wn4);

    dim3 blk(NTHREADS);
    qkv_kernel<<<dim3((B_ * S_) / BM, D_ / BN, 3), blk, SMEM_BYTES>>>(bq, bk, bv);
    scores_kernel<<<dim3(S_ / BM, S_ / BN, B_), blk, SMEM_BYTES>>>();
    softmax_kernel<<<dim3(B_ * S_), 256>>>();
    av_kernel<<<dim3(S_ / BM, D_ / BN, B_), blk, SMEM_BYTES>>>(out);
}

// round 9
// speedup vs baseline: 1.7060x; 1.5802x over previous
#include <cuda_runtime.h>
#include <cuda_fp16.h>
#include <cstdint>
#include <math.h>

// Problem constants
#define B_ 4
#define S_ 2048
#define E_ 1024
#define D_ 1024

// GEMM tiling
#define BM 128
#define BN 128
#define BK 32
#define PK 40                        // smem k-pitch in fp16 elems (80B, conflict-free)
#define NTHREADS 256

#define SUB_ELEMS (BM * PK)          // one operand tile: 5120 fp16 = 10240 B
#define STAGE_ELEMS (3 * SUB_ELEMS)  // Ah, Bh, Bl per stage = 30720 B
#define NSTAGE 3
#define SMEM_BYTES (NSTAGE * STAGE_ELEMS * 2)   // 92160 B

// ---------------- gmem scratch (static device arrays) ----------------
static __device__ __half g_Xh [(size_t)B_ * S_ * E_];
static __device__ __half g_Wh [3 * (size_t)D_ * E_];
static __device__ __half g_Wl [3 * (size_t)D_ * E_];
static __device__ __half g_Qh [(size_t)B_ * S_ * D_];
static __device__ __half g_Kh [(size_t)B_ * S_ * D_];
static __device__ __half g_Kl [(size_t)B_ * S_ * D_];
static __device__ __half g_Vth[(size_t)B_ * D_ * S_];   // V transposed [b][d][s]
static __device__ __half g_Vtl[(size_t)B_ * D_ * S_];
static __device__ float  g_A  [(size_t)B_ * S_ * S_];   // raw scores
static __device__ __half g_Ph [(size_t)B_ * S_ * S_];   // softmax probs (hi only)

__device__ __forceinline__ unsigned smem_u32(const void* p) {
    return (unsigned)__cvta_generic_to_shared(p);
}
__device__ __forceinline__ void cp16(void* sdst, const void* gsrc) {
    asm volatile("cp.async.cg.shared.global [%0], [%1], 16;"
                 :: "r"(smem_u32(sdst)), "l"(gsrc));
}
#define CP_COMMIT() asm volatile("cp.async.commit_group;" ::: "memory")

#define LDSM_X4(R0, R1, R2, R3, ADDR)                                          \
    asm volatile("ldmatrix.sync.aligned.m8n8.x4.shared.b16 {%0,%1,%2,%3}, [%4];" \
                 : "=r"(R0), "=r"(R1), "=r"(R2), "=r"(R3) : "r"(ADDR))
#define LDSM_X2(R0, R1, ADDR)                                                  \
    asm volatile("ldmatrix.sync.aligned.m8n8.x2.shared.b16 {%0,%1}, [%2];"      \
                 : "=r"(R0), "=r"(R1) : "r"(ADDR))
#define MMA_F16(D, A0, A1, A2, A3, Bq0, Bq1)                                   \
    asm volatile("mma.sync.aligned.m16n8k16.row.col.f32.f16.f16.f32 "           \
                 "{%0,%1,%2,%3}, {%4,%5,%6,%7}, {%8,%9}, {%0,%1,%2,%3};"        \
                 : "+f"(D[0]), "+f"(D[1]), "+f"(D[2]), "+f"(D[3])               \
                 : "r"(A0), "r"(A1), "r"(A2), "r"(A3), "r"(Bq0), "r"(Bq1))

__device__ __forceinline__ __half lo_of(float v, __half h) {
    return __float2half(v - __half2float(h));
}

// ---------------------------------------------------------------------------
// Pre-split fp32 -> fp16 hi (+ optional lo) in gmem. n4 = elem count / 4.
// ---------------------------------------------------------------------------
__global__ void split_kernel(const float* __restrict__ src,
                             __half* __restrict__ hi,
                             __half* __restrict__ lo, int n4)
{
    int i = blockIdx.x * blockDim.x + threadIdx.x;
    if (i >= n4) return;
    float4 v = ((const float4*)src)[i];
    __half h0 = __float2half(v.x), h1 = __float2half(v.y);
    __half h2 = __float2half(v.z), h3 = __float2half(v.w);
    *(__half2*)(hi + 4 * i)     = __halves2half2(h0, h1);
    *(__half2*)(hi + 4 * i + 2) = __halves2half2(h2, h3);
    if (lo) {
        *(__half2*)(lo + 4 * i)     = __halves2half2(lo_of(v.x, h0), lo_of(v.y, h1));
        *(__half2*)(lo + 4 * i + 2) = __halves2half2(lo_of(v.z, h2), lo_of(v.w, h3));
    }
}

// ---------------------------------------------------------------------------
// 128x128x32 NT GEMM tile: fp16 2-term split (A hi-only, B hi+lo),
// D ~= Ah*Bh + Ah*Bl, fp32 accumulate. 3-stage cp.async pipeline with a
// SINGLE __syncthreads per K-chunk.
//   OMODE 0: fp32 out (Cf)
//   OMODE 1: fp16 hi out (Ch)
//   OMODE 2: fp16 hi+lo out (Ch/Cl)
//   OMODE 3: fp16 hi+lo out transposed per-batch ([d][s], for Vt)
// ---------------------------------------------------------------------------
template <int OMODE, bool HAS_BIAS, bool KLIMIT>
__device__ __forceinline__ void gemm_body(
    const __half* __restrict__ Ahg,
    const __half* __restrict__ Bhg, const __half* __restrict__ Blg,
    const float* __restrict__ bias, float* __restrict__ Cf,
    __half* __restrict__ Ch, __half* __restrict__ Cl,
    int K, int ldb, int ldc, float scale)
{
    extern __shared__ __half smem[];
    const int t = threadIdx.x, lane = t & 31, wid = t >> 5;
    const int wm = (wid >> 2) * 64;     // warp row base (0/64)
    const int wn = (wid & 3) * 32;      // warp col base (0..96)
    const int row0 = blockIdx.x * BM, col0 = blockIdx.y * BN;

    int kmax = K;
    if (KLIMIT) { int lim = (blockIdx.x + 1) * BM; kmax = lim < K ? lim : K; }
    const int chunks = kmax / BK;       // >= 4 always

    float acc[4][4][4];
#pragma unroll
    for (int i = 0; i < 4; i++)
#pragma unroll
        for (int j = 0; j < 4; j++)
#pragma unroll
            for (int r = 0; r < 4; r++) acc[i][j][r] = 0.f;

    auto issue = [&](int c, int b) {
        __half* st = smem + b * STAGE_ELEMS;
        const int k0 = c * BK;
#pragma unroll
        for (int h = 0; h < 2; h++) {
            const int cid = t + 256 * h;       // 0..511
            const int row = cid >> 2;          // 0..127
            const int kc  = (cid & 3) * 8;     // 0,8,16,24 (16B chunks)
            __half* s = st + row * PK + kc;
            cp16(s,                 Ahg + (size_t)(row0 + row) * K   + k0 + kc);
            const size_t gb = (size_t)(col0 + row) * ldb + k0 + kc;
            cp16(s + SUB_ELEMS,     Bhg + gb);
            cp16(s + 2 * SUB_ELEMS, Blg + gb);
        }
    };

    auto compute = [&](int b) {
        __half* Ah = smem + b * STAGE_ELEMS;
        __half* Bh = Ah + SUB_ELEMS;
        __half* Bl = Ah + 2 * SUB_ELEMS;
#pragma unroll
        for (int kk = 0; kk < 2; kk++) {
            unsigned a[4][4], bh[4][2], bl[4][2];
            const int arow = wm + (lane & 15);
            const int acol = kk * 16 + (lane >> 4) * 8;
#pragma unroll
            for (int mt = 0; mt < 4; mt++) {
                const int off = (arow + mt * 16) * PK + acol;
                LDSM_X4(a[mt][0], a[mt][1], a[mt][2], a[mt][3], smem_u32(&Ah[off]));
            }
            const int brow = wn + (lane & 7);
            const int bcol = kk * 16 + ((lane >> 3) & 1) * 8;
#pragma unroll
            for (int nt = 0; nt < 4; nt++) {
                const int off = (brow + nt * 8) * PK + bcol;
                LDSM_X2(bh[nt][0], bh[nt][1], smem_u32(&Bh[off]));
                LDSM_X2(bl[nt][0], bl[nt][1], smem_u32(&Bl[off]));
            }
#pragma unroll
            for (int mt = 0; mt < 4; mt++)
#pragma unroll
                for (int nt = 0; nt < 4; nt++) {
                    MMA_F16(acc[mt][nt], a[mt][0], a[mt][1], a[mt][2], a[mt][3],
                            bh[nt][0], bh[nt][1]);
                    MMA_F16(acc[mt][nt], a[mt][0], a[mt][1], a[mt][2], a[mt][3],
                            bl[nt][0], bl[nt][1]);
                }
        }
    };

    // ---- 3-stage cp.async mainloop, one barrier per chunk ----
    issue(0, 0); CP_COMMIT();
    issue(1, 1); CP_COMMIT();
    for (int c = 0; c < chunks; c++) {
        if (c + 1 < chunks)
            asm volatile("cp.async.wait_group 1;" ::: "memory");
        else
            asm volatile("cp.async.wait_group 0;" ::: "memory");
        __syncthreads();
        compute(c % NSTAGE);
        // issue(c+2) writes buffer (c+2)%3 == (c-1)%3, which every warp
        // finished reading before the barrier above was released.
        if (c + 2 < chunks) { issue(c + 2, (c + 2) % NSTAGE); CP_COMMIT(); }
    }

    // ---- epilogue ----
    const int g = lane >> 2, q = lane & 3;
#pragma unroll
    for (int mt = 0; mt < 4; mt++) {
#pragma unroll
        for (int nt = 0; nt < 4; nt++) {
            const int r = row0 + wm + mt * 16 + g;
            const int c = col0 + wn + nt * 8 + 2 * q;
            float v0 = acc[mt][nt][0] * scale;
            float v1 = acc[mt][nt][1] * scale;
            float v2 = acc[mt][nt][2] * scale;
            float v3 = acc[mt][nt][3] * scale;
            if (HAS_BIAS) {
                const float b0 = bias[c], b1 = bias[c + 1];
                v0 += b0; v1 += b1; v2 += b0; v3 += b1;
            }
            if (OMODE == 0) {
                *(float2*)&Cf[(size_t)r * ldc + c]       = make_float2(v0, v1);
                *(float2*)&Cf[(size_t)(r + 8) * ldc + c] = make_float2(v2, v3);
            } else {
                __half h0 = __float2half(v0), h1 = __float2half(v1);
                __half h2 = __float2half(v2), h3 = __float2half(v3);
                if (OMODE == 1 || OMODE == 2) {
                    *(__half2*)&Ch[(size_t)r * ldc + c]       = __halves2half2(h0, h1);
                    *(__half2*)&Ch[(size_t)(r + 8) * ldc + c] = __halves2half2(h2, h3);
                    if (OMODE == 2) {
                        *(__half2*)&Cl[(size_t)r * ldc + c] =
                            __halves2half2(lo_of(v0, h0), lo_of(v1, h1));
                        *(__half2*)&Cl[(size_t)(r + 8) * ldc + c] =
                            __halves2half2(lo_of(v2, h2), lo_of(v3, h3));
                    }
                } else {
                    const int batch = row0 >> 11;   // tiles never straddle batches
                    const size_t base = (size_t)batch * D_ * S_;
                    const int s = r & (S_ - 1);
                    Ch[base + (size_t)c * S_ + s]           = h0;
                    Ch[base + (size_t)(c + 1) * S_ + s]     = h1;
                    Ch[base + (size_t)c * S_ + s + 8]       = h2;
                    Ch[base + (size_t)(c + 1) * S_ + s + 8] = h3;
                    Cl[base + (size_t)c * S_ + s]           = lo_of(v0, h0);
                    Cl[base + (size_t)(c + 1) * S_ + s]     = lo_of(v1, h1);
                    Cl[base + (size_t)c * S_ + s + 8]       = lo_of(v2, h2);
                    Cl[base + (size_t)(c + 1) * S_ + s + 8] = lo_of(v3, h3);
                }
            }
        }
    }
}

// ---------------------------------------------------------------------------
// Stage 1: Q/K/V = X @ W^T + b. Q hi-only (A operand later); K and Vt hi+lo
// (B operands later); Vt transposed so the AV gemm is NT.
// ---------------------------------------------------------------------------
__global__ __launch_bounds__(NTHREADS, 2) void qkv_kernel(
    const float* __restrict__ bq, const float* __restrict__ bk,
    const float* __restrict__ bv)
{
    const size_t wo = (size_t)blockIdx.z * D_ * E_;
    if (blockIdx.z == 0)
        gemm_body<1, true, false>(g_Xh, g_Wh + wo, g_Wl + wo, bq,
                                  nullptr, g_Qh, nullptr, E_, E_, D_, 1.0f);
    else if (blockIdx.z == 1)
        gemm_body<2, true, false>(g_Xh, g_Wh + wo, g_Wl + wo, bk,
                                  nullptr, g_Kh, g_Kl, E_, E_, D_, 1.0f);
    else
        gemm_body<3, true, false>(g_Xh, g_Wh + wo, g_Wl + wo, bv,
                                  nullptr, g_Vth, g_Vtl, E_, E_, D_, 1.0f);
}

// ---------------------------------------------------------------------------
// Stage 2: scores A = (Q @ K^T) / sqrt(D); tiles above the diagonal skipped.
// ---------------------------------------------------------------------------
__global__ __launch_bounds__(NTHREADS, 2) void scores_kernel()
{
    if (blockIdx.y > blockIdx.x) return;
    const size_t bo = (size_t)blockIdx.z * S_ * D_;
    gemm_body<0, false, false>(g_Qh + bo, g_Kh + bo, g_Kl + bo, nullptr,
                               g_A + (size_t)blockIdx.z * S_ * S_, nullptr, nullptr,
                               D_, D_, S_, 0.03125f /* 1/sqrt(1024) */);
}

// ---------------------------------------------------------------------------
// Stage 3: causal softmax -> fp16 probs (zero-filled past the diagonal so AV
// can read clamped full tiles).
// ---------------------------------------------------------------------------
__global__ __launch_bounds__(256) void softmax_kernel()
{
    const int gid = blockIdx.x;                 // b*S + m
    const float* row = g_A + (size_t)gid * S_;
    __half* ph = g_Ph + (size_t)gid * S_;
    const int m = gid & (S_ - 1);
    const int n = m + 1;
    const int t = threadIdx.x;
    __shared__ float red[8];

    float mx = -INFINITY;
    for (int i = t; i < n; i += 256) mx = fmaxf(mx, row[i]);
#pragma unroll
    for (int o = 16; o > 0; o >>= 1) mx = fmaxf(mx, __shfl_xor_sync(~0u, mx, o));
    if ((t & 31) == 0) red[t >> 5] = mx;
    __syncthreads();
    mx = red[0];
#pragma unroll
    for (int w = 1; w < 8; w++) mx = fmaxf(mx, red[w]);
    __syncthreads();

    float s = 0.f;
    for (int i = t; i < n; i += 256) s += __expf(row[i] - mx);
#pragma unroll
    for (int o = 16; o > 0; o >>= 1) s += __shfl_xor_sync(~0u, s, o);
    if ((t & 31) == 0) red[t >> 5] = s;
    __syncthreads();
    s = 0.f;
#pragma unroll
    for (int w = 0; w < 8; w++) s += red[w];
    const float inv = 1.f / s;

    for (int i = t; i < S_; i += 256) {
        float p = (i < n) ? __expf(row[i] - mx) * inv : 0.f;
        ph[i] = __float2half(p);
    }
}

// ---------------------------------------------------------------------------
// Stage 4: O = P @ Vt^T (NT gemm), K-loop clamped causally.
// ---------------------------------------------------------------------------
__global__ __launch_bounds__(NTHREADS, 2) void av_kernel(float* __restrict__ out)
{
    const size_t b = blockIdx.z;
    gemm_body<0, false, true>(g_Ph + b * (size_t)S_ * S_,
                              g_Vth + b * (size_t)D_ * S_, g_Vtl + b * (size_t)D_ * S_,
                              nullptr, out + b * (size_t)S_ * D_, nullptr, nullptr,
                              S_, S_, D_, 1.0f);
}

// ---------------------------------------------------------------------------
// Inputs (metadata order): X, Wq, bq, Wk, bk, Wv, bv, mask (mask is static
// triu(k=1) -> applied analytically). cudaFuncSetAttribute /
// cudaGetSymbolAddress are host-side queries, safe under graph capture.
// ---------------------------------------------------------------------------
extern "C" void kernel_launch(void* const* d_in, const int* in_sizes, int n_in,
                              void* d_out, int out_size)
{
    const float* X  = (const float*)d_in[0];
    const float* Wq = (const float*)d_in[1];
    const float* bq = (const float*)d_in[2];
    const float* Wk = (const float*)d_in[3];
    const float* bk = (const float*)d_in[4];
    const float* Wv = (const float*)d_in[5];
    const float* bv = (const float*)d_in[6];
    float* out = (float*)d_out;

    cudaFuncSetAttribute(qkv_kernel,    cudaFuncAttributeMaxDynamicSharedMemorySize, SMEM_BYTES);
    cudaFuncSetAttribute(scores_kernel, cudaFuncAttributeMaxDynamicSharedMemorySize, SMEM_BYTES);
    cudaFuncSetAttribute(av_kernel,     cudaFuncAttributeMaxDynamicSharedMemorySize, SMEM_BYTES);

    __half *xh, *wh, *wl;
    cudaGetSymbolAddress((void**)&xh, g_Xh);
    cudaGetSymbolAddress((void**)&wh, g_Wh);
    cudaGetSymbolAddress((void**)&wl, g_Wl);

    const int xn4 = B_ * S_ * E_ / 4;          // 2M
    const int wn4 = D_ * E_ / 4;               // 256K
    split_kernel<<<(xn4 + 255) / 256, 256>>>(X, xh, nullptr, xn4);
    split_kernel<<<(wn4 + 255) / 256, 256>>>(Wq, wh,               wl,               wn4);
    split_kernel<<<(wn4 + 255) / 256, 256>>>(Wk, wh + D_ * E_,     wl + D_ * E_,     wn4);
    split_kernel<<<(wn4 + 255) / 256, 256>>>(Wv, wh + 2 * D_ * E_, wl + 2 * D_ * E_, wn4);

    dim3 blk(NTHREADS);
    qkv_kernel<<<dim3((B_ * S_) / BM, D_ / BN, 3), blk, SMEM_BYTES>>>(bq, bk, bv);
    scores_kernel<<<dim3(S_ / BM, S_ / BN, B_), blk, SMEM_BYTES>>>();
    softmax_kernel<<<dim3(B_ * S_), 256>>>();
    av_kernel<<<dim3(S_ / BM, D_ / BN, B_), blk, SMEM_BYTES>>>(out);
}